// round 13
// baseline (speedup 1.0000x reference)
#include <cuda_runtime.h>
#include <cuda_fp16.h>
#include <cstdint>

// DotReluAttention: out = relu(Q @ K^T / 64) @ V ; B=2,H=8,S=4096,D=64 fp32.
// v10: v9 compute path (fp16 m16n8k16, ldmatrix, 3-stage cp.async, fused
// G1->reg->G2) resized to 256 threads / BM=128 so TWO CTAs co-reside per SM:
// 8 warps/SMSP from independent CTAs hide barrier/load exposure.

#define SEQ 4096
#define HD  64
#define BM  128
#define BN  128
#define NTH 256
#define NITER (SEQ/BN)    // 32
#define NK16  (BN/16)     // 8
#define BH    16

// smem geometry (bytes)
#define KROWB 144              // K row: 128B data + 16 pad
#define VROWB 272              // V^T row: 256B data + 16 pad
#define KTILEB (BN*KROWB)      // 18432
#define VTILEB (64*VROWB)      // 17408
#define BUFB   (KTILEB+VTILEB) // 35840
#define SMEM_BYTES (3*BUFB)    // 107520 (x2 CTAs = 215040 <= 227KB)
#define QROWW 36               // Q staging row stride in words (144B)

// pre-converted fp16 images
__device__ __align__(16) uint32_t g_K16 [(size_t)BH*SEQ*32];     // [bh*S+n][k/2]   8MB
__device__ __align__(16) uint32_t g_V16T[(size_t)BH*64*2048];    // [bh][hd][kv/2]  8MB

__device__ __forceinline__ uint32_t pack2(float a, float b) {
    __half2 h = __floats2half2_rn(a, b);
    return *reinterpret_cast<uint32_t*>(&h);
}
__device__ __forceinline__ void mma16(float* c, const uint32_t* a,
                                      uint32_t b0, uint32_t b1) {
    asm volatile(
        "mma.sync.aligned.m16n8k16.row.col.f32.f16.f16.f32 "
        "{%0,%1,%2,%3}, {%4,%5,%6,%7}, {%8,%9}, {%0,%1,%2,%3};\n"
        : "+f"(c[0]), "+f"(c[1]), "+f"(c[2]), "+f"(c[3])
        : "r"(a[0]), "r"(a[1]), "r"(a[2]), "r"(a[3]), "r"(b0), "r"(b1));
}
#define LDSM4(r, a) \
    asm volatile("ldmatrix.sync.aligned.m8n8.x4.shared.b16 {%0,%1,%2,%3}, [%4];" \
        : "=r"((r)[0]), "=r"((r)[1]), "=r"((r)[2]), "=r"((r)[3]) : "r"(a))
#define CP16(dst, src) \
    asm volatile("cp.async.cg.shared.global [%0], [%1], 16;" :: "r"(dst), "l"(src) : "memory")
#define CP_COMMIT() asm volatile("cp.async.commit_group;" ::: "memory")
#define CP_WAIT(n)  asm volatile("cp.async.wait_group %0;" :: "n"(n) : "memory")

__device__ __forceinline__ uint32_t smem_u32(const void* p) {
    uint32_t a;
    asm("{ .reg .u64 t; cvta.to.shared.u64 t, %1; cvt.u32.u64 %0, t; }" : "=r"(a) : "l"(p));
    return a;
}

// ---------- kernel 1: K fp32 -> fp16 natural rows ----------
__global__ __launch_bounds__(512)
void convert_k(const float* __restrict__ K) {
    int t = blockIdx.x * 512 + threadIdx.x;   // 0..262143
    int row = t >> 2, j = t & 3;
    const float4* src = (const float4*)(K + (size_t)row * HD + j * 16);
    float4 a = src[0], b = src[1], c = src[2], d = src[3];
    uint32_t* dst = g_K16 + (size_t)row * 32 + j * 8;
    dst[0] = pack2(a.x, a.y); dst[1] = pack2(a.z, a.w);
    dst[2] = pack2(b.x, b.y); dst[3] = pack2(b.z, b.w);
    dst[4] = pack2(c.x, c.y); dst[5] = pack2(c.z, c.w);
    dst[6] = pack2(d.x, d.y); dst[7] = pack2(d.z, d.w);
}

// ---------- kernel 2: V fp32 -> fp16 transposed [hd][kv] ----------
__global__ __launch_bounds__(128)
void convert_vT(const float* __restrict__ V) {
    __shared__ uint32_t sT[64 * 132];          // [hd][kvpair], stride 132 words
    int bh  = blockIdx.y;
    int kvb = blockIdx.x * 256;                // 256 kv rows per block
    int t   = threadIdx.x;                     // kv-pair index 0..127
    const float* r0 = V + ((size_t)bh * SEQ + kvb + 2 * t) * HD;
    const float* r1 = r0 + HD;
    #pragma unroll
    for (int j = 0; j < 16; j++) {             // hd 4j..4j+3
        float4 a = ((const float4*)r0)[j];
        float4 b = ((const float4*)r1)[j];
        sT[(4*j+0)*132 + t] = pack2(a.x, b.x);
        sT[(4*j+1)*132 + t] = pack2(a.y, b.y);
        sT[(4*j+2)*132 + t] = pack2(a.z, b.z);
        sT[(4*j+3)*132 + t] = pack2(a.w, b.w);
    }
    __syncthreads();
    uint32_t* out = g_V16T + (size_t)bh * 64 * 2048 + (kvb >> 1) + t;
    #pragma unroll
    for (int j = 0; j < 64; j++)
        out[(size_t)j * 2048] = sT[j * 132 + t];
}

// issue cp.async for one K/V tile into buffer at byte-address sb
__device__ __forceinline__ void issue_tile(uint32_t sb, const char* kSrc,
                                           const char* vSrc, int tid) {
    #pragma unroll
    for (int i = 0; i < 4; i++) {              // K: 1024 chunks of 16B
        int c = tid + i * NTH;
        CP16(sb + (c >> 3) * KROWB + (c & 7) * 16, kSrc + c * 16);
    }
    #pragma unroll
    for (int i = 0; i < 4; i++) {              // V^T: 1024 chunks (64 rows x 16)
        int c = tid + i * NTH;
        CP16(sb + KTILEB + (c >> 4) * VROWB + (c & 15) * 16,
             vSrc + (size_t)(c >> 4) * 8192 + (c & 15) * 16);
    }
}

// ---------- kernel 3: fused attention ----------
__global__ __launch_bounds__(NTH, 2)
void dot_relu_attn_v10(const float* __restrict__ Q, float* __restrict__ O) {
    extern __shared__ uint32_t sm[];
    const uint32_t sbase = smem_u32(sm);

    const int tid  = threadIdx.x;
    const int warp = tid >> 5;
    const int lane = tid & 31;
    const int gid  = lane >> 2;
    const int tig  = lane & 3;
    const int m0   = warp * 16;

    const int bh = blockIdx.y;
    const int qb = blockIdx.x * BM;
    const float* Qp = Q + ((size_t)bh * SEQ + qb) * HD;
    float*       Op = O + ((size_t)bh * SEQ + qb) * HD;

    // ---- Stage Q (natural [m][k] rows, stride 144B) ----
    #pragma unroll
    for (int i = 0; i < 8; i++) {
        int lin = tid + i * NTH;               // 2048 float4
        int row = lin >> 4, c4 = lin & 15;
        float4 v = *(const float4*)(Qp + row * HD + c4 * 4);
        sm[row * QROWW + 2 * c4]     = pack2(v.x, v.y);
        sm[row * QROWW + 2 * c4 + 1] = pack2(v.z, v.w);
    }
    __syncthreads();

    // ---- Q A-fragments via ldmatrix.x4 ----
    uint32_t qa[4][4];
    {
        uint32_t qaddr = sbase
            + (m0 + ((lane >> 3) & 1) * 8 + (lane & 7)) * (QROWW * 4)
            + (lane >> 4) * 16;
        #pragma unroll
        for (int kt = 0; kt < 4; kt++) LDSM4(qa[kt], qaddr + kt * 32);
    }
    __syncthreads();   // staging area freed for K/V buffers

    float oacc[8][4];
    #pragma unroll
    for (int b = 0; b < 8; b++)
        #pragma unroll
        for (int c = 0; c < 4; c++) oacc[b][c] = 0.f;

    const uint32_t kfrag_off = (lane & 7) * KROWB + (lane >> 3) * 16;
    const uint32_t vfrag_off = KTILEB
        + ((lane >> 4) * 8 + (lane & 7)) * VROWB + ((lane >> 3) & 1) * 16;

    const char* kTile0 = (const char*)(g_K16 + ((size_t)bh * SEQ) * 32);
    const char* vTile0 = (const char*)(g_V16T + (size_t)bh * 64 * 2048);

    // prologue: tiles 0 and 1 in flight
    issue_tile(sbase,        kTile0,            vTile0,       tid); CP_COMMIT();
    issue_tile(sbase + BUFB, kTile0 + BN * 128, vTile0 + 256, tid); CP_COMMIT();

    int cb = 0;                 // compute buffer index (it % 3)
    #pragma unroll 1
    for (int it = 0; it < NITER; it++) {
        if (it + 1 < NITER) { CP_WAIT(1); } else { CP_WAIT(0); }
        __syncthreads();        // tile it visible; everyone past compute(it-1)

        if (it + 2 < NITER) {
            int ib = cb + 2; if (ib >= 3) ib -= 3;
            issue_tile(sbase + ib * BUFB,
                       kTile0 + (size_t)(it + 2) * BN * 128,
                       vTile0 + (size_t)(it + 2) * 256, tid);
            CP_COMMIT();
        }

        const uint32_t kaddr = sbase + cb * BUFB + kfrag_off;
        const uint32_t vaddr = sbase + cb * BUFB + vfrag_off;

        #pragma unroll 2
        for (int nk = 0; nk < NK16; nk++) {
            float s0[4], s1[4];
            {   // S cols 16nk+0..7
                uint32_t ka = kaddr + (2 * nk) * (8 * KROWB);
                uint32_t kr[8];
                LDSM4(kr,     ka);
                LDSM4(kr + 4, ka + 64);
                float ta[4] = {0.f, 0.f, 0.f, 0.f};
                float tb[4] = {0.f, 0.f, 0.f, 0.f};
                mma16(ta, qa[0], kr[0], kr[1]);
                mma16(tb, qa[1], kr[2], kr[3]);
                mma16(ta, qa[2], kr[4], kr[5]);
                mma16(tb, qa[3], kr[6], kr[7]);
                s0[0] = ta[0] + tb[0]; s0[1] = ta[1] + tb[1];
                s0[2] = ta[2] + tb[2]; s0[3] = ta[3] + tb[3];
            }
            {   // S cols 16nk+8..15
                uint32_t ka = kaddr + (2 * nk + 1) * (8 * KROWB);
                uint32_t kr[8];
                LDSM4(kr,     ka);
                LDSM4(kr + 4, ka + 64);
                float ta[4] = {0.f, 0.f, 0.f, 0.f};
                float tb[4] = {0.f, 0.f, 0.f, 0.f};
                mma16(ta, qa[0], kr[0], kr[1]);
                mma16(tb, qa[1], kr[2], kr[3]);
                mma16(ta, qa[2], kr[4], kr[5]);
                mma16(tb, qa[3], kr[6], kr[7]);
                s1[0] = ta[0] + tb[0]; s1[1] = ta[1] + tb[1];
                s1[2] = ta[2] + tb[2]; s1[3] = ta[3] + tb[3];
            }
            // relu + pack: GEMM1 C-fragment == GEMM2 A-fragment
            uint32_t pa[4];
            pa[0] = pack2(fmaxf(s0[0], 0.f), fmaxf(s0[1], 0.f));
            pa[1] = pack2(fmaxf(s0[2], 0.f), fmaxf(s0[3], 0.f));
            pa[2] = pack2(fmaxf(s1[0], 0.f), fmaxf(s1[1], 0.f));
            pa[3] = pack2(fmaxf(s1[2], 0.f), fmaxf(s1[3], 0.f));

            // GEMM2: V^T fragments via 4x ldmatrix.x4
            uint32_t vr[16];
            uint32_t va = vaddr + nk * 32;
            LDSM4(vr,      va);
            LDSM4(vr + 4,  va + 16 * VROWB);
            LDSM4(vr + 8,  va + 32 * VROWB);
            LDSM4(vr + 12, va + 48 * VROWB);
            #pragma unroll
            for (int n2 = 0; n2 < 8; n2++)
                mma16(oacc[n2], pa, vr[2 * n2], vr[2 * n2 + 1]);
        }
        cb++; if (cb == 3) cb = 0;
    }

    // ---- Epilogue: O_out = O / 64 ----
    {
        float* r0 = Op + (size_t)(m0 + gid) * HD;
        float* r1 = r0 + 8 * HD;
        #pragma unroll
        for (int n2 = 0; n2 < 8; n2++) {
            int col = n2 * 8 + 2 * tig;
            *(float2*)(r0 + col) = make_float2(oacc[n2][0] * 0.015625f,
                                               oacc[n2][1] * 0.015625f);
            *(float2*)(r1 + col) = make_float2(oacc[n2][2] * 0.015625f,
                                               oacc[n2][3] * 0.015625f);
        }
    }
}

extern "C" void kernel_launch(void* const* d_in, const int* in_sizes, int n_in,
                              void* d_out, int out_size) {
    const float* q = (const float*)d_in[0];
    const float* k = (const float*)d_in[1];
    const float* v = (const float*)d_in[2];
    float* o = (float*)d_out;

    convert_k<<<512, 512>>>(k);
    convert_vT<<<dim3(SEQ / 256, BH), 128>>>(v);

    cudaFuncSetAttribute(dot_relu_attn_v10,
                         cudaFuncAttributeMaxDynamicSharedMemorySize, SMEM_BYTES);
    dim3 grid(SEQ / BM, BH);
    dot_relu_attn_v10<<<grid, NTH, SMEM_BYTES>>>(q, o);
}

// round 14
// speedup vs baseline: 1.0833x; 1.0833x over previous
#include <cuda_runtime.h>
#include <cuda_fp16.h>
#include <cstdint>

// DotReluAttention: out = relu(Q @ K^T / 64) @ V ; B=2,H=8,S=4096,D=64 fp32.
// v11 = v8 (best, 219us) + software-pipelined chunk loop: G1 of chunk nk+1
// overlaps G2 of chunk nk, breaking the G1->pack->G2 serial chain.
// fp16 m16n8k16, 512 threads, BM=256, BN=128, cp.async double buffering.

#define SEQ 4096
#define HD  64
#define BM  256
#define BN  128
#define NTH 512
#define NITER (SEQ/BN)    // 32
#define NK16  (BN/16)     // 8
#define BH    16

// smem geometry (32-bit words)
#define QSTR 40           // Q staging rows (startup only)
#define KSTR 40           // K rows: 32 data words + 8 pad
#define VSTR 72           // V pair-rows: 64 data words + 8 pad
#define KWORDS (BN*KSTR)              // 5120
#define BUFW   (KWORDS + (BN/2)*VSTR) // 9728 words per buffer
#define SMEM_WORDS (2*BUFW)           // 19456 (Q staging 10240 fits inside)
#define SMEM_BYTES (SMEM_WORDS*4)     // 77824

// pre-converted fp16 images (packed half2 words)
__device__ __align__(16) uint32_t g_K16[(size_t)BH*SEQ*32];       // 8MB
__device__ __align__(16) uint32_t g_V16[(size_t)BH*(SEQ/2)*64];   // 8MB

__device__ __forceinline__ uint32_t pack2(float a, float b) {
    __half2 h = __floats2half2_rn(a, b);
    return *reinterpret_cast<uint32_t*>(&h);
}
__device__ __forceinline__ void mma16(float* c, const uint32_t* a,
                                      uint32_t b0, uint32_t b1) {
    asm volatile(
        "mma.sync.aligned.m16n8k16.row.col.f32.f16.f16.f32 "
        "{%0,%1,%2,%3}, {%4,%5,%6,%7}, {%8,%9}, {%0,%1,%2,%3};\n"
        : "+f"(c[0]), "+f"(c[1]), "+f"(c[2]), "+f"(c[3])
        : "r"(a[0]), "r"(a[1]), "r"(a[2]), "r"(a[3]), "r"(b0), "r"(b1));
}
__device__ __forceinline__ int wpos(int w) {    // pair-permute within 8-word chunk
    return (w & ~7) + 2 * (w & 3) + ((w & 4) >> 2);
}
__device__ __forceinline__ uint32_t smem_u32(const void* p) {
    uint32_t a;
    asm("{ .reg .u64 t; cvta.to.shared.u64 t, %1; cvt.u32.u64 %0, t; }" : "=r"(a) : "l"(p));
    return a;
}

// ---------------- kernel 1: fp32 -> packed fp16 images ----------------
__global__ __launch_bounds__(512)
void convert_kv(const float* __restrict__ K, const float* __restrict__ V) {
    int t = blockIdx.x * 512 + threadIdx.x;   // 0 .. 262143
    {   // K: row-major, wpos-permuted pairs
        int row = t >> 2, j = t & 3;
        const float4* src = (const float4*)(K + (size_t)row * HD + j * 16);
        float4 a = src[0], b = src[1], c = src[2], d = src[3];
        uint32_t* dst = g_K16 + (size_t)row * 32 + j * 8;
        dst[0] = pack2(a.x, a.y); dst[2] = pack2(a.z, a.w);
        dst[4] = pack2(b.x, b.y); dst[6] = pack2(b.z, b.w);
        dst[1] = pack2(c.x, c.y); dst[3] = pack2(c.z, c.w);
        dst[5] = pack2(d.x, d.y); dst[7] = pack2(d.z, d.w);
    }
    {   // V: vertical kv-pair packing: word = {V[2pr][n], V[2pr+1][n]}
        int pr = t >> 3, j = t & 7;
        const float* s0 = V + (size_t)(2 * pr) * HD + j * 8;
        float4 r0a = ((const float4*)s0)[0], r0b = ((const float4*)s0)[1];
        float4 r1a = ((const float4*)(s0 + HD))[0], r1b = ((const float4*)(s0 + HD))[1];
        uint32_t* dst = g_V16 + (size_t)pr * 64 + j * 8;
        dst[0] = pack2(r0a.x, r1a.x); dst[1] = pack2(r0a.y, r1a.y);
        dst[2] = pack2(r0a.z, r1a.z); dst[3] = pack2(r0a.w, r1a.w);
        dst[4] = pack2(r0b.x, r1b.x); dst[5] = pack2(r0b.y, r1b.y);
        dst[6] = pack2(r0b.z, r1b.z); dst[7] = pack2(r0b.w, r1b.w);
    }
}

// issue cp.async copies for one K/V tile into smem buffer at byte addr sbuf
__device__ __forceinline__ void issue_tile(int bh, int it, uint32_t sbuf, int tid) {
    const char* kbase = (const char*)(g_K16 + ((size_t)bh * SEQ + it * BN) * 32);
    #pragma unroll
    for (int i = 0; i < 2; i++) {
        int c = tid + i * NTH;                 // 1024 chunks of 16B
        uint32_t dst = sbuf + (c >> 3) * (KSTR * 4) + (c & 7) * 16;
        asm volatile("cp.async.cg.shared.global [%0], [%1], 16;"
                     :: "r"(dst), "l"(kbase + c * 16) : "memory");
    }
    const char* vbase = (const char*)(g_V16 + ((size_t)bh * (SEQ/2) + it * (BN/2)) * 64);
    uint32_t svbuf = sbuf + KWORDS * 4;
    #pragma unroll
    for (int i = 0; i < 2; i++) {
        int c = tid + i * NTH;                 // 1024 chunks of 16B
        uint32_t dst = svbuf + (c >> 4) * (VSTR * 4) + (c & 15) * 16;
        asm volatile("cp.async.cg.shared.global [%0], [%1], 16;"
                     :: "r"(dst), "l"(vbase + c * 16) : "memory");
    }
}
#define CP_COMMIT() asm volatile("cp.async.commit_group;" ::: "memory")
#define CP_WAIT(n)  asm volatile("cp.async.wait_group %0;" :: "n"(n) : "memory")

// GEMM1 for one 16-col chunk nk: s[0..3] = cols 16nk+0..7, s[4..7] = +8..15
__device__ __forceinline__ void g1_chunk(const uint32_t* sK,
                                         const uint32_t qa[4][4],
                                         int gid, int tig, int nk, float* s) {
    #pragma unroll
    for (int h = 0; h < 2; h++) {
        const uint32_t* kb = &sK[((2 * nk + h) * 8 + gid) * KSTR + 2 * tig];
        uint2 b0 = *(const uint2*)(kb);
        uint2 b1 = *(const uint2*)(kb + 8);
        uint2 b2 = *(const uint2*)(kb + 16);
        uint2 b3 = *(const uint2*)(kb + 24);
        float ta[4] = {0.f, 0.f, 0.f, 0.f};
        float tb[4] = {0.f, 0.f, 0.f, 0.f};
        mma16(ta, qa[0], b0.x, b0.y);
        mma16(tb, qa[1], b1.x, b1.y);
        mma16(ta, qa[2], b2.x, b2.y);
        mma16(tb, qa[3], b3.x, b3.y);
        s[4*h+0] = ta[0] + tb[0]; s[4*h+1] = ta[1] + tb[1];
        s[4*h+2] = ta[2] + tb[2]; s[4*h+3] = ta[3] + tb[3];
    }
}

// ---------------- kernel 2: fused attention ----------------
__global__ __launch_bounds__(NTH, 1)
void dot_relu_attn_v11(const float* __restrict__ Q, float* __restrict__ O) {
    extern __shared__ uint32_t sm[];
    const uint32_t sbase = smem_u32(sm);

    const int tid  = threadIdx.x;
    const int warp = tid >> 5;
    const int lane = tid & 31;
    const int gid  = lane >> 2;
    const int tig  = lane & 3;
    const int m0   = warp * 16;

    const int bh = blockIdx.y;
    const int qb = blockIdx.x * BM;
    const float* Qp = Q + ((size_t)bh * SEQ + qb) * HD;
    float*       Op = O + ((size_t)bh * SEQ + qb) * HD;

    // ---- Stage Q (one-time; staging overlaps the K/V buffers) ----
    #pragma unroll
    for (int i = 0; i < 8; i++) {
        int lin = tid + i * NTH;
        int row = lin >> 4, c4 = lin & 15;
        float4 v = *(const float4*)(Qp + row * HD + c4 * 4);
        sm[row * QSTR + wpos(2 * c4)]     = pack2(v.x, v.y);
        sm[row * QSTR + wpos(2 * c4 + 1)] = pack2(v.z, v.w);
    }
    __syncthreads();
    uint32_t qa[4][4];
    #pragma unroll
    for (int kt = 0; kt < 4; kt++) {
        const uint32_t* p = &sm[(m0 + gid) * QSTR + kt * 8 + 2 * tig];
        uint2 lo = *(const uint2*)p;
        uint2 hi = *(const uint2*)(p + 8 * QSTR);
        qa[kt][0] = lo.x; qa[kt][1] = hi.x;
        qa[kt][2] = lo.y; qa[kt][3] = hi.y;
    }
    __syncthreads();   // staging done; buffers free

    float oacc[8][4];
    #pragma unroll
    for (int b = 0; b < 8; b++)
        #pragma unroll
        for (int c = 0; c < 4; c++) oacc[b][c] = 0.f;

    // prologue: start tile 0
    issue_tile(bh, 0, sbase, tid);
    CP_COMMIT();

    #pragma unroll 1
    for (int it = 0; it < NITER; it++) {
        if (it + 1 < NITER) {
            issue_tile(bh, it + 1, sbase + ((it + 1) & 1) * (BUFW * 4), tid);
            CP_COMMIT();
            CP_WAIT(1);            // tile it has landed
        } else {
            CP_WAIT(0);
        }
        __syncthreads();           // make all threads' copies visible

        const uint32_t* sK = sm + (it & 1) * BUFW;
        const uint32_t* sV = sK + KWORDS;

        // ---- software-pipelined chunk loop: G1(nk+1) overlaps G2(nk) ----
        float scur[8];
        g1_chunk(sK, qa, gid, tig, 0, scur);
        #pragma unroll
        for (int nk = 0; nk < NK16; nk++) {
            float snxt[8];
            if (nk + 1 < NK16)
                g1_chunk(sK, qa, gid, tig, nk + 1, snxt);

            // relu + pack: GEMM1 C-fragment == GEMM2 A-fragment
            uint32_t pa[4];
            pa[0] = pack2(fmaxf(scur[0], 0.f), fmaxf(scur[1], 0.f));
            pa[1] = pack2(fmaxf(scur[2], 0.f), fmaxf(scur[3], 0.f));
            pa[2] = pack2(fmaxf(scur[4], 0.f), fmaxf(scur[5], 0.f));
            pa[3] = pack2(fmaxf(scur[6], 0.f), fmaxf(scur[7], 0.f));

            // GEMM2: B from packed V (2x LDS.32), 8 independent accumulators
            const uint32_t* vb = &sV[(8 * nk + tig) * VSTR + gid];
            #pragma unroll
            for (int n2 = 0; n2 < 8; n2++) {
                uint32_t b0 = vb[n2 * 8];
                uint32_t b1 = vb[4 * VSTR + n2 * 8];
                mma16(oacc[n2], pa, b0, b1);
            }

            #pragma unroll
            for (int x = 0; x < 8; x++) scur[x] = snxt[x];
        }
        __syncthreads();           // done reading buf it&1 before it's rewritten
    }

    // ---- Epilogue: O_out = O / 64 ----
    {
        float* r0 = Op + (size_t)(m0 + gid) * HD;
        float* r1 = r0 + 8 * HD;
        #pragma unroll
        for (int n2 = 0; n2 < 8; n2++) {
            int col = n2 * 8 + 2 * tig;
            *(float2*)(r0 + col) = make_float2(oacc[n2][0] * 0.015625f,
                                               oacc[n2][1] * 0.015625f);
            *(float2*)(r1 + col) = make_float2(oacc[n2][2] * 0.015625f,
                                               oacc[n2][3] * 0.015625f);
        }
    }
}

extern "C" void kernel_launch(void* const* d_in, const int* in_sizes, int n_in,
                              void* d_out, int out_size) {
    const float* q = (const float*)d_in[0];
    const float* k = (const float*)d_in[1];
    const float* v = (const float*)d_in[2];
    float* o = (float*)d_out;

    convert_kv<<<512, 512>>>(k, v);

    cudaFuncSetAttribute(dot_relu_attn_v11,
                         cudaFuncAttributeMaxDynamicSharedMemorySize, SMEM_BYTES);
    dim3 grid(SEQ / BM, BH);
    dot_relu_attn_v11<<<grid, NTH, SMEM_BYTES>>>(q, o);
}